// round 13
// baseline (speedup 1.0000x reference)
#include <cuda_runtime.h>
#include <mma.h>
#include <cstdint>

using namespace nvcuda;

#define N_NODES 100000
#define N_EDGES 1600000
#define HID 128
#define NUM_LAYERS 10
#define NUM_GRAPHS 64
#define NUM_CLASSES 2

// ---------------- scratch (device globals; no runtime allocation) ----------------
// row-padded (+128) arrays so tail-block wmma frag loads/stores never fault
__device__ __align__(16) float g_x[(size_t)N_NODES * HID];
__device__ __align__(16) float g_h[(size_t)(N_NODES + 128) * HID];
__device__ __align__(16) float g_hh[(size_t)(N_NODES + 128) * HID];  // tf32 hi of h
__device__ __align__(16) float g_hl[(size_t)(N_NODES + 128) * HID];  // tf32 lo of h
__device__ __align__(16) float g_th[(size_t)(N_NODES + 128) * HID];  // tf32 hi of T
__device__ __align__(16) float g_tl[(size_t)(N_NODES + 128) * HID];  // tf32 lo of T
__device__ __align__(16) float g_w1h[NUM_LAYERS * HID * HID];
__device__ __align__(16) float g_w1l[NUM_LAYERS * HID * HID];
__device__ __align__(16) float g_w2h[NUM_LAYERS * HID * HID];
__device__ __align__(16) float g_w2l[NUM_LAYERS * HID * HID];
__device__ int   g_deg[N_NODES];
__device__ int   g_rowptr[N_NODES + 1];
__device__ int   g_fill[N_NODES];
__device__ int   g_ssrc[N_EDGES];
__device__ int   g_bsums[256];
__device__ __align__(16) float g_pool[NUM_GRAPHS * HID];
__device__ float g_cnt[NUM_GRAPHS];
__device__ __align__(16) float g_cls[NUM_GRAPHS * HID];

// ---------------- weight pre-split into tf32 hi/lo (once per launch) --------------
__global__ void wprep_kernel(const float* __restrict__ W1,
                             const float* __restrict__ W2) {
    int i = blockIdx.x * blockDim.x + threadIdx.x;
    if (i < NUM_LAYERS * HID * HID) {
        float w = W1[i];
        float h = wmma::__float_to_tf32(w);
        g_w1h[i] = h;
        g_w1l[i] = wmma::__float_to_tf32(w - h);
        w = W2[i];
        h = wmma::__float_to_tf32(w);
        g_w2h[i] = h;
        g_w2l[i] = wmma::__float_to_tf32(w - h);
    }
}

// ---------------- CSR build ----------------
__global__ void zero_kernel() {
    int i = blockIdx.x * blockDim.x + threadIdx.x;
    if (i < N_NODES) g_deg[i] = 0;
    if (i < NUM_GRAPHS * HID) g_pool[i] = 0.f;
    if (i < NUM_GRAPHS) g_cnt[i] = 0.f;
}

__global__ void hist_kernel(const int* __restrict__ dst) {
    int e = blockIdx.x * blockDim.x + threadIdx.x;
    if (e < N_EDGES) atomicAdd(&g_deg[dst[e]], 1);
}

__global__ void scan1_kernel() {
    __shared__ int s[512];
    int tid = threadIdx.x;
    int i = blockIdx.x * 512 + tid;
    int v = (i < N_NODES) ? g_deg[i] : 0;
    s[tid] = v;
    __syncthreads();
    for (int off = 1; off < 512; off <<= 1) {
        int add = (tid >= off) ? s[tid - off] : 0;
        __syncthreads();
        s[tid] += add;
        __syncthreads();
    }
    if (i < N_NODES) g_rowptr[i] = s[tid] - v;
    if (tid == 511) g_bsums[blockIdx.x] = s[511];
}

__global__ void scan2_kernel(int nblk) {
    __shared__ int s[256];
    int tid = threadIdx.x;
    int v = (tid < nblk) ? g_bsums[tid] : 0;
    s[tid] = v;
    __syncthreads();
    for (int off = 1; off < 256; off <<= 1) {
        int add = (tid >= off) ? s[tid - off] : 0;
        __syncthreads();
        s[tid] += add;
        __syncthreads();
    }
    if (tid < nblk) g_bsums[tid] = s[tid] - v;
}

__global__ void scan3_kernel() {
    int i = blockIdx.x * blockDim.x + threadIdx.x;
    if (i < N_NODES) {
        int rp = g_rowptr[i] + g_bsums[i >> 9];
        g_rowptr[i] = rp;
        g_fill[i] = rp;
    }
    if (i == 0) g_rowptr[N_NODES] = N_EDGES;
}

__global__ void scatter_kernel(const int* __restrict__ src,
                               const int* __restrict__ dst) {
    int e = blockIdx.x * blockDim.x + threadIdx.x;
    if (e < N_EDGES) {
        int d = dst[e];
        int p = atomicAdd(&g_fill[d], 1);
        g_ssrc[p] = src[e];
    }
}

// ------- aggregation: h[v] = (1+eps)*x[v] + sum_in x[u]; writes h + tf32 hi/lo ----
__global__ void aggr_kernel(const float* __restrict__ xin_ext,
                            const float* __restrict__ eps, int layer, int use_gx) {
    int gw = (blockIdx.x * blockDim.x + threadIdx.x) >> 5;
    int lane = threadIdx.x & 31;
    if (gw >= N_NODES) return;
    const float* x = use_gx ? g_x : xin_ext;
    float ep1 = 1.0f + eps[layer];
    const float4* xv = (const float4*)x;
    float4 b = __ldg(&xv[(size_t)gw * 32 + lane]);
    float4 a0 = make_float4(b.x * ep1, b.y * ep1, b.z * ep1, b.w * ep1);
    float4 a1 = make_float4(0.f, 0.f, 0.f, 0.f);
    float4 a2 = a1, a3 = a1;
    int s = g_rowptr[gw], e = g_rowptr[gw + 1];
    int i = s;
    for (; i + 4 <= e; i += 4) {
        int s0 = g_ssrc[i], s1 = g_ssrc[i + 1], s2 = g_ssrc[i + 2], s3 = g_ssrc[i + 3];
        float4 v0 = __ldg(&xv[(size_t)s0 * 32 + lane]);
        float4 v1 = __ldg(&xv[(size_t)s1 * 32 + lane]);
        float4 v2 = __ldg(&xv[(size_t)s2 * 32 + lane]);
        float4 v3 = __ldg(&xv[(size_t)s3 * 32 + lane]);
        a0.x += v0.x; a0.y += v0.y; a0.z += v0.z; a0.w += v0.w;
        a1.x += v1.x; a1.y += v1.y; a1.z += v1.z; a1.w += v1.w;
        a2.x += v2.x; a2.y += v2.y; a2.z += v2.z; a2.w += v2.w;
        a3.x += v3.x; a3.y += v3.y; a3.z += v3.z; a3.w += v3.w;
    }
    for (; i < e; i++) {
        int s0 = g_ssrc[i];
        float4 v0 = __ldg(&xv[(size_t)s0 * 32 + lane]);
        a1.x += v0.x; a1.y += v0.y; a1.z += v0.z; a1.w += v0.w;
    }
    a0.x += a1.x + a2.x + a3.x;
    a0.y += a1.y + a2.y + a3.y;
    a0.z += a1.z + a2.z + a3.z;
    a0.w += a1.w + a2.w + a3.w;
    size_t idx = (size_t)gw * 32 + lane;
    ((float4*)g_h)[idx] = a0;
    float4 hi, lo;
    hi.x = wmma::__float_to_tf32(a0.x); lo.x = wmma::__float_to_tf32(a0.x - hi.x);
    hi.y = wmma::__float_to_tf32(a0.y); lo.y = wmma::__float_to_tf32(a0.y - hi.y);
    hi.z = wmma::__float_to_tf32(a0.z); lo.z = wmma::__float_to_tf32(a0.z - hi.z);
    hi.w = wmma::__float_to_tf32(a0.w); lo.w = wmma::__float_to_tf32(a0.w - hi.w);
    ((float4*)g_hh)[idx] = hi;
    ((float4*)g_hl)[idx] = lo;
}

// ================= wmma pre-split 3xTF32 fused MLP ================================
// 256 threads = 8 warps, each warp owns 16 rows of a 128-row tile.
// Operands pre-split (NO in-loop split ALU): A*B ~= Ahi*Bhi + Alo*Bhi + Ahi*Blo.
// Intermediate T hi/lo via global scratch (own-warp write->read, L1-coherent).
#define WM_BM 128

typedef wmma::fragment<wmma::matrix_a, 16, 16, 8, wmma::precision::tf32, wmma::row_major> AF;
typedef wmma::fragment<wmma::matrix_b, 16, 16, 8, wmma::precision::tf32, wmma::row_major> BF;
typedef wmma::fragment<wmma::accumulator, 16, 16, 8, float> CF;

__global__ void __launch_bounds__(256)
mlp_t3_kernel(const float* __restrict__ xin_ext,
              const float* __restrict__ b1, const float* __restrict__ b2,
              int add_h, int use_gx, int layer) {
    __shared__ __align__(32) float Cs[8][16 * 16];   // per-warp C staging, 8 KB

    const float* xin = use_gx ? g_x : xin_ext;
    const float* W1h = g_w1h + (size_t)layer * HID * HID;
    const float* W1l = g_w1l + (size_t)layer * HID * HID;
    const float* W2h = g_w2h + (size_t)layer * HID * HID;
    const float* W2l = g_w2l + (size_t)layer * HID * HID;

    int w = threadIdx.x >> 5;
    int lane = threadIdx.x & 31;
    int wrow = blockIdx.x * WM_BM + w * 16;   // may exceed N_NODES; arrays padded
    float* cs = Cs[w];

    CF c[8];
    AF ah, al;
    BF bh, bl;

    // ---- GEMM1: C = split(h) @ split(W1)
#pragma unroll
    for (int nt = 0; nt < 8; nt++) wmma::fill_fragment(c[nt], 0.f);
#pragma unroll 4
    for (int k = 0; k < 16; k++) {
        wmma::load_matrix_sync(ah, g_hh + (size_t)wrow * HID + k * 8, HID);
        wmma::load_matrix_sync(al, g_hl + (size_t)wrow * HID + k * 8, HID);
#pragma unroll
        for (int nt = 0; nt < 8; nt++) {
            wmma::load_matrix_sync(bh, W1h + (size_t)(k * 8) * HID + nt * 16, HID);
            wmma::load_matrix_sync(bl, W1l + (size_t)(k * 8) * HID + nt * 16, HID);
            wmma::mma_sync(c[nt], ah, bh, c[nt]);
            wmma::mma_sync(c[nt], al, bh, c[nt]);
            wmma::mma_sync(c[nt], ah, bl, c[nt]);
        }
    }
    // epilogue1: T = relu(C + b1); split exact tf32 hi/lo -> global scratch
#pragma unroll
    for (int nt = 0; nt < 8; nt++) {
        wmma::store_matrix_sync(cs, c[nt], 16, wmma::mem_row_major);
        __syncwarp();
#pragma unroll
        for (int i = 0; i < 8; i++) {
            int idx = lane + i * 32;        // 0..255
            int r = idx >> 4, cc = idx & 15;
            int col = nt * 16 + cc;
            float v = fmaxf(cs[r * 16 + cc] + __ldg(&b1[col]), 0.f);
            float hi = wmma::__float_to_tf32(v);
            size_t base = (size_t)(wrow + r) * HID + col;
            g_th[base] = hi;
            g_tl[base] = wmma::__float_to_tf32(v - hi);
        }
        __syncwarp();
    }

    // ---- GEMM2: C = split(T) @ split(W2)
#pragma unroll
    for (int nt = 0; nt < 8; nt++) wmma::fill_fragment(c[nt], 0.f);
#pragma unroll 4
    for (int k = 0; k < 16; k++) {
        // plain (non-__ldg) loads: g_th/g_tl just written by this warp
        wmma::load_matrix_sync(ah, g_th + (size_t)wrow * HID + k * 8, HID);
        wmma::load_matrix_sync(al, g_tl + (size_t)wrow * HID + k * 8, HID);
#pragma unroll
        for (int nt = 0; nt < 8; nt++) {
            wmma::load_matrix_sync(bh, W2h + (size_t)(k * 8) * HID + nt * 16, HID);
            wmma::load_matrix_sync(bl, W2l + (size_t)(k * 8) * HID + nt * 16, HID);
            wmma::mma_sync(c[nt], ah, bh, c[nt]);
            wmma::mma_sync(c[nt], al, bh, c[nt]);
            wmma::mma_sync(c[nt], ah, bl, c[nt]);
        }
    }
    // epilogue2: out = relu(C + b2 [+ h]) + xin
#pragma unroll
    for (int nt = 0; nt < 8; nt++) {
        wmma::store_matrix_sync(cs, c[nt], 16, wmma::mem_row_major);
        __syncwarp();
#pragma unroll
        for (int i = 0; i < 8; i++) {
            int idx = lane + i * 32;
            int r = idx >> 4, cc = idx & 15;
            int grow = wrow + r;
            if (grow < N_NODES) {
                int col = nt * 16 + cc;
                size_t base = (size_t)grow * HID + col;
                float v = cs[r * 16 + cc] + __ldg(&b2[col]);
                if (add_h) v += g_h[base];
                g_x[base] = fmaxf(v, 0.f) + xin[base];
            }
        }
        __syncwarp();
    }
}

// ---------------- mean pool over sorted batch ----------------
#define POOL_CHUNK 256
__global__ void pool_kernel(const int* __restrict__ batch) {
    int d = threadIdx.x;  // 128
    int n0 = blockIdx.x * POOL_CHUNK;
    int n1 = n0 + POOL_CHUNK; if (n1 > N_NODES) n1 = N_NODES;
    int cur = batch[n0];
    float local = 0.f;
    for (int n = n0; n < n1; n++) {
        int b = batch[n];
        if (b != cur) {
            atomicAdd(&g_pool[cur * HID + d], local);
            local = 0.f; cur = b;
        }
        local += g_x[(size_t)n * HID + d];
    }
    atomicAdd(&g_pool[cur * HID + d], local);
    if (d == 0) {
        int c2 = batch[n0];
        float cl = 0.f;
        for (int n = n0; n < n1; n++) {
            int b = batch[n];
            if (b != c2) { atomicAdd(&g_cnt[c2], cl); cl = 0.f; c2 = b; }
            cl += 1.f;
        }
        atomicAdd(&g_cnt[c2], cl);
    }
}

// ---------------- classifier ----------------
__global__ void cls1_kernel(const float* __restrict__ Wc1,
                            const float* __restrict__ bc1) {
    __shared__ float Ps[128];
    int g = blockIdx.x;
    int t = threadIdx.x;
    float inv = 1.f / fmaxf(g_cnt[g], 1.f);
    Ps[t] = g_pool[g * HID + t] * inv;
    __syncthreads();
    float s = bc1[t];
#pragma unroll 4
    for (int k = 0; k < 128; k++) s += Ps[k] * __ldg(&Wc1[k * 128 + t]);
    g_cls[g * HID + t] = fmaxf(s, 0.f);
}

__global__ void cls2_kernel(const float* __restrict__ Wc2,
                            const float* __restrict__ bc2,
                            float* __restrict__ out) {
    int t = threadIdx.x;
    int g = t >> 1, c = t & 1;
    float s = bc2[c];
#pragma unroll 4
    for (int k = 0; k < 128; k++) s += g_cls[g * HID + k] * __ldg(&Wc2[k * 2 + c]);
    out[t] = s;
}

// ---------------- launch (pure kernel launches — graph-capture safe) -------------
// NOTE: never do pointer arithmetic on __device__ symbols here (host shadow trap).
extern "C" void kernel_launch(void* const* d_in, const int* in_sizes, int n_in,
                              void* d_out, int out_size) {
    const float* x     = (const float*)d_in[0];
    const int*   ei    = (const int*)d_in[1];     // int32 (JAX x64 disabled)
    const int*   batch = (const int*)d_in[2];     // int32
    const float* eps   = (const float*)d_in[3];
    const float* W1    = (const float*)d_in[4];
    const float* b1    = (const float*)d_in[5];
    const float* W2    = (const float*)d_in[6];
    const float* b2    = (const float*)d_in[7];
    const float* Wc1   = (const float*)d_in[8];
    const float* bc1   = (const float*)d_in[9];
    const float* Wc2   = (const float*)d_in[10];
    const float* bc2   = (const float*)d_in[11];
    const int* src = ei;
    const int* dst = ei + N_EDGES;

    const int nblk_scan = (N_NODES + 511) / 512;            // 196
    const int nblk_mlp  = (N_NODES + WM_BM - 1) / WM_BM;    // 782

    wprep_kernel<<<(NUM_LAYERS * HID * HID + 255) / 256, 256>>>(W1, W2);
    zero_kernel<<<(N_NODES + 255) / 256, 256>>>();
    hist_kernel<<<(N_EDGES + 255) / 256, 256>>>(dst);
    scan1_kernel<<<nblk_scan, 512>>>();
    scan2_kernel<<<1, 256>>>(nblk_scan);
    scan3_kernel<<<(N_NODES + 255) / 256, 256>>>();
    scatter_kernel<<<(N_EDGES + 255) / 256, 256>>>(src, dst);

    for (int i = 0; i < NUM_LAYERS; i++) {
        int use_gx = (i > 0) ? 1 : 0;
        aggr_kernel<<<(N_NODES + 7) / 8, 256>>>(x, eps, i, use_gx);
        mlp_t3_kernel<<<nblk_mlp, 256>>>(
            x,
            b1 + (size_t)i * HID, b2 + (size_t)i * HID,
            (i > 0) ? 1 : 0, use_gx, i);
    }

    pool_kernel<<<(N_NODES + POOL_CHUNK - 1) / POOL_CHUNK, 128>>>(batch);
    cls1_kernel<<<NUM_GRAPHS, 128>>>(Wc1, bc1);
    cls2_kernel<<<1, 128>>>(Wc2, bc2, (float*)d_out);
}

// round 14
// speedup vs baseline: 1.7338x; 1.7338x over previous
#include <cuda_runtime.h>
#include <cstdint>

#define N_NODES 100000
#define N_EDGES 1600000
#define HID 128
#define NUM_LAYERS 10
#define NUM_GRAPHS 64
#define NUM_CLASSES 2

// ---------------- scratch (device globals; no runtime allocation) ----------------
__device__ __align__(16) float g_x[(size_t)N_NODES * HID];
__device__ __align__(16) float g_h[(size_t)N_NODES * HID];
__device__ int   g_deg[N_NODES];
__device__ int   g_rowptr[N_NODES + 1];
__device__ int   g_fill[N_NODES];
__device__ int   g_ssrc[N_EDGES];
__device__ int   g_bsums[256];
__device__ __align__(16) float g_pool[NUM_GRAPHS * HID];
__device__ float g_cnt[NUM_GRAPHS];
__device__ __align__(16) float g_cls[NUM_GRAPHS * HID];

// ---------------- packed f32x2 helpers (FFMA2 — 2 fp32 MACs per issue) ------------
__device__ __forceinline__ unsigned long long pack2(float x) {
    unsigned long long r;
    asm("mov.b64 %0, {%1, %1};" : "=l"(r) : "f"(x));
    return r;
}
__device__ __forceinline__ void ffma2(unsigned long long& d,
                                      unsigned long long a,
                                      unsigned long long b) {
    asm("fma.rn.f32x2 %0, %1, %2, %0;" : "+l"(d) : "l"(a), "l"(b));
}
__device__ __forceinline__ void unpack2(unsigned long long v, float& lo, float& hi) {
    asm("mov.b64 {%0, %1}, %2;" : "=f"(lo), "=f"(hi) : "l"(v));
}

// ---------------- CSR build ----------------
__global__ void zero_kernel() {
    int i = blockIdx.x * blockDim.x + threadIdx.x;
    if (i < N_NODES) g_deg[i] = 0;
    if (i < NUM_GRAPHS * HID) g_pool[i] = 0.f;
    if (i < NUM_GRAPHS) g_cnt[i] = 0.f;
}

__global__ void hist_kernel(const int* __restrict__ dst) {
    int e = blockIdx.x * blockDim.x + threadIdx.x;
    if (e < N_EDGES) atomicAdd(&g_deg[dst[e]], 1);
}

__global__ void scan1_kernel() {
    __shared__ int s[512];
    int tid = threadIdx.x;
    int i = blockIdx.x * 512 + tid;
    int v = (i < N_NODES) ? g_deg[i] : 0;
    s[tid] = v;
    __syncthreads();
    for (int off = 1; off < 512; off <<= 1) {
        int add = (tid >= off) ? s[tid - off] : 0;
        __syncthreads();
        s[tid] += add;
        __syncthreads();
    }
    if (i < N_NODES) g_rowptr[i] = s[tid] - v;
    if (tid == 511) g_bsums[blockIdx.x] = s[511];
}

__global__ void scan2_kernel(int nblk) {
    __shared__ int s[256];
    int tid = threadIdx.x;
    int v = (tid < nblk) ? g_bsums[tid] : 0;
    s[tid] = v;
    __syncthreads();
    for (int off = 1; off < 256; off <<= 1) {
        int add = (tid >= off) ? s[tid - off] : 0;
        __syncthreads();
        s[tid] += add;
        __syncthreads();
    }
    if (tid < nblk) g_bsums[tid] = s[tid] - v;
}

__global__ void scan3_kernel() {
    int i = blockIdx.x * blockDim.x + threadIdx.x;
    if (i < N_NODES) {
        int rp = g_rowptr[i] + g_bsums[i >> 9];
        g_rowptr[i] = rp;
        g_fill[i] = rp;
    }
    if (i == 0) g_rowptr[N_NODES] = N_EDGES;
}

__global__ void scatter_kernel(const int* __restrict__ src,
                               const int* __restrict__ dst) {
    int e = blockIdx.x * blockDim.x + threadIdx.x;
    if (e < N_EDGES) {
        int d = dst[e];
        int p = atomicAdd(&g_fill[d], 1);
        g_ssrc[p] = src[e];
    }
}

// ---------------- per-layer aggregation: h[v] = (1+eps)*x[v] + sum_in x[u] --------
__global__ void aggr_kernel(const float* __restrict__ xin_ext,
                            const float* __restrict__ eps, int layer, int use_gx) {
    int gw = (blockIdx.x * blockDim.x + threadIdx.x) >> 5;
    int lane = threadIdx.x & 31;
    if (gw >= N_NODES) return;
    const float* x = use_gx ? g_x : xin_ext;
    float ep1 = 1.0f + eps[layer];
    const float4* xv = (const float4*)x;
    float4 b = __ldg(&xv[(size_t)gw * 32 + lane]);
    float4 a0 = make_float4(b.x * ep1, b.y * ep1, b.z * ep1, b.w * ep1);
    float4 a1 = make_float4(0.f, 0.f, 0.f, 0.f);
    float4 a2 = a1, a3 = a1;
    int s = g_rowptr[gw], e = g_rowptr[gw + 1];
    int i = s;
    for (; i + 4 <= e; i += 4) {
        int s0 = g_ssrc[i], s1 = g_ssrc[i + 1], s2 = g_ssrc[i + 2], s3 = g_ssrc[i + 3];
        float4 v0 = __ldg(&xv[(size_t)s0 * 32 + lane]);
        float4 v1 = __ldg(&xv[(size_t)s1 * 32 + lane]);
        float4 v2 = __ldg(&xv[(size_t)s2 * 32 + lane]);
        float4 v3 = __ldg(&xv[(size_t)s3 * 32 + lane]);
        a0.x += v0.x; a0.y += v0.y; a0.z += v0.z; a0.w += v0.w;
        a1.x += v1.x; a1.y += v1.y; a1.z += v1.z; a1.w += v1.w;
        a2.x += v2.x; a2.y += v2.y; a2.z += v2.z; a2.w += v2.w;
        a3.x += v3.x; a3.y += v3.y; a3.z += v3.z; a3.w += v3.w;
    }
    for (; i < e; i++) {
        int s0 = g_ssrc[i];
        float4 v0 = __ldg(&xv[(size_t)s0 * 32 + lane]);
        a1.x += v0.x; a1.y += v0.y; a1.z += v0.z; a1.w += v0.w;
    }
    a0.x += a1.x + a2.x + a3.x;
    a0.y += a1.y + a2.y + a3.y;
    a0.z += a1.z + a2.z + a3.z;
    a0.w += a1.w + a2.w + a3.w;
    ((float4*)g_h)[(size_t)gw * 32 + lane] = a0;
}

// ---------------- fused MLP: g_x = relu(relu(h@W1+b1)@W2 + b2 [+h]) + xin ---------
// R6 structure (BM=64, single smem tile) with packed-f32x2 FFMA2 inner loops.
#define BM 64
#define HSTR 132  // padded row stride in floats

__global__ void __launch_bounds__(256)
mlp_kernel(const float* __restrict__ xin_ext,
           const float* __restrict__ W1, const float* __restrict__ b1,
           const float* __restrict__ W2, const float* __restrict__ b2,
           int add_h, int use_gx) {
    __shared__ float Bs[BM * HSTR];

    const float* xin = use_gx ? g_x : xin_ext;
    int t = threadIdx.x;
    int row0 = blockIdx.x * BM;
    int nrows = N_NODES - row0; if (nrows > BM) nrows = BM;

    // load H tile (BM x 128) into shared
    for (int i = t; i < BM * 32; i += 256) {
        int r = i >> 5, c = i & 31;
        float4 v = (r < nrows)
            ? *((const float4*)(g_h + (size_t)(row0 + r) * HID) + c)
            : make_float4(0.f, 0.f, 0.f, 0.f);
        *((float4*)&Bs[r * HSTR + c * 4]) = v;
    }
    __syncthreads();

    int tx = t & 15, ty = t >> 4;   // 16 x 16 thread grid
    int cb = tx * 8;                // 8 cols per thread (4 f32x2 pairs)
    int rb = ty * 4;                // 4 rows per thread

    unsigned long long acc[4][4];
#pragma unroll
    for (int r = 0; r < 4; r++)
#pragma unroll
        for (int j = 0; j < 4; j++) acc[r][j] = 0ull;

#pragma unroll 4
    for (int k = 0; k < 128; k++) {
        // B operand: 8 consecutive floats = 4 f32x2 packed pairs (32B-aligned)
        ulonglong2 w01 = __ldg((const ulonglong2*)&W1[k * 128 + cb]);
        ulonglong2 w23 = __ldg((const ulonglong2*)&W1[k * 128 + cb + 4]);
        unsigned long long bv[4] = {w01.x, w01.y, w23.x, w23.y};
#pragma unroll
        for (int r = 0; r < 4; r++) {
            unsigned long long ar = pack2(Bs[(rb + r) * HSTR + k]);
#pragma unroll
            for (int j = 0; j < 4; j++) ffma2(acc[r][j], ar, bv[j]);
        }
    }
    __syncthreads();  // all GEMM1 reads of Bs done — safe to overwrite

    // write T = relu(acc + b1) into the SAME buffer
#pragma unroll
    for (int r = 0; r < 4; r++)
#pragma unroll
        for (int j = 0; j < 4; j++) {
            float lo, hi;
            unpack2(acc[r][j], lo, hi);
            int col = cb + j * 2;
            Bs[(rb + r) * HSTR + col]     = fmaxf(lo + __ldg(&b1[col]), 0.f);
            Bs[(rb + r) * HSTR + col + 1] = fmaxf(hi + __ldg(&b1[col + 1]), 0.f);
        }
    __syncthreads();

#pragma unroll
    for (int r = 0; r < 4; r++)
#pragma unroll
        for (int j = 0; j < 4; j++) acc[r][j] = 0ull;

#pragma unroll 4
    for (int k = 0; k < 128; k++) {
        ulonglong2 w01 = __ldg((const ulonglong2*)&W2[k * 128 + cb]);
        ulonglong2 w23 = __ldg((const ulonglong2*)&W2[k * 128 + cb + 4]);
        unsigned long long bv[4] = {w01.x, w01.y, w23.x, w23.y};
#pragma unroll
        for (int r = 0; r < 4; r++) {
            unsigned long long ar = pack2(Bs[(rb + r) * HSTR + k]);
#pragma unroll
            for (int j = 0; j < 4; j++) ffma2(acc[r][j], ar, bv[j]);
        }
    }

    // epilogue: + b2 [+ h reread] relu + xin, store
#pragma unroll
    for (int r = 0; r < 4; r++) {
        int row = rb + r;
        if (row < nrows) {
            size_t base = (size_t)(row0 + row) * HID + cb;
            float acf[8];
#pragma unroll
            for (int j = 0; j < 4; j++) unpack2(acc[r][j], acf[j * 2], acf[j * 2 + 1]);
            float4 h0 = make_float4(0.f, 0.f, 0.f, 0.f), h1 = h0;
            if (add_h) {
                h0 = *((const float4*)(g_h + base));
                h1 = *((const float4*)(g_h + base + 4));
            }
            float hv[8] = {h0.x, h0.y, h0.z, h0.w, h1.x, h1.y, h1.z, h1.w};
            float4 xi0 = *((const float4*)(xin + base));
            float4 xi1 = *((const float4*)(xin + base + 4));
            float xv[8] = {xi0.x, xi0.y, xi0.z, xi0.w, xi1.x, xi1.y, xi1.z, xi1.w};
            float o[8];
#pragma unroll
            for (int c = 0; c < 8; c++) {
                float v = acf[c] + __ldg(&b2[cb + c]) + hv[c];
                o[c] = fmaxf(v, 0.f) + xv[c];
            }
            *((float4*)(g_x + base))     = make_float4(o[0], o[1], o[2], o[3]);
            *((float4*)(g_x + base + 4)) = make_float4(o[4], o[5], o[6], o[7]);
        }
    }
}

// ---------------- mean pool over sorted batch ----------------
#define POOL_CHUNK 256
__global__ void pool_kernel(const int* __restrict__ batch) {
    int d = threadIdx.x;  // 128
    int n0 = blockIdx.x * POOL_CHUNK;
    int n1 = n0 + POOL_CHUNK; if (n1 > N_NODES) n1 = N_NODES;
    int cur = batch[n0];
    float local = 0.f;
    for (int n = n0; n < n1; n++) {
        int b = batch[n];
        if (b != cur) {
            atomicAdd(&g_pool[cur * HID + d], local);
            local = 0.f; cur = b;
        }
        local += g_x[(size_t)n * HID + d];
    }
    atomicAdd(&g_pool[cur * HID + d], local);
    if (d == 0) {
        int c2 = batch[n0];
        float cl = 0.f;
        for (int n = n0; n < n1; n++) {
            int b = batch[n];
            if (b != c2) { atomicAdd(&g_cnt[c2], cl); cl = 0.f; c2 = b; }
            cl += 1.f;
        }
        atomicAdd(&g_cnt[c2], cl);
    }
}

// ---------------- classifier ----------------
__global__ void cls1_kernel(const float* __restrict__ Wc1,
                            const float* __restrict__ bc1) {
    __shared__ float Ps[128];
    int g = blockIdx.x;
    int t = threadIdx.x;
    float inv = 1.f / fmaxf(g_cnt[g], 1.f);
    Ps[t] = g_pool[g * HID + t] * inv;
    __syncthreads();
    float s = bc1[t];
#pragma unroll 4
    for (int k = 0; k < 128; k++) s += Ps[k] * __ldg(&Wc1[k * 128 + t]);
    g_cls[g * HID + t] = fmaxf(s, 0.f);
}

__global__ void cls2_kernel(const float* __restrict__ Wc2,
                            const float* __restrict__ bc2,
                            float* __restrict__ out) {
    int t = threadIdx.x;
    int g = t >> 1, c = t & 1;
    float s = bc2[c];
#pragma unroll 4
    for (int k = 0; k < 128; k++) s += g_cls[g * HID + k] * __ldg(&Wc2[k * 2 + c]);
    out[t] = s;
}

// ---------------- launch (pure kernel launches — graph-capture safe) -------------
// NOTE: never do pointer arithmetic on __device__ symbols here (host shadow trap).
extern "C" void kernel_launch(void* const* d_in, const int* in_sizes, int n_in,
                              void* d_out, int out_size) {
    const float* x     = (const float*)d_in[0];
    const int*   ei    = (const int*)d_in[1];     // int32 (JAX x64 disabled)
    const int*   batch = (const int*)d_in[2];     // int32
    const float* eps   = (const float*)d_in[3];
    const float* W1    = (const float*)d_in[4];
    const float* b1    = (const float*)d_in[5];
    const float* W2    = (const float*)d_in[6];
    const float* b2    = (const float*)d_in[7];
    const float* Wc1   = (const float*)d_in[8];
    const float* bc1   = (const float*)d_in[9];
    const float* Wc2   = (const float*)d_in[10];
    const float* bc2   = (const float*)d_in[11];
    const int* src = ei;
    const int* dst = ei + N_EDGES;

    const int nblk_scan = (N_NODES + 511) / 512;  // 196

    zero_kernel<<<(N_NODES + 255) / 256, 256>>>();
    hist_kernel<<<(N_EDGES + 255) / 256, 256>>>(dst);
    scan1_kernel<<<nblk_scan, 512>>>();
    scan2_kernel<<<1, 256>>>(nblk_scan);
    scan3_kernel<<<(N_NODES + 255) / 256, 256>>>();
    scatter_kernel<<<(N_EDGES + 255) / 256, 256>>>(src, dst);

    for (int i = 0; i < NUM_LAYERS; i++) {
        int use_gx = (i > 0) ? 1 : 0;
        aggr_kernel<<<(N_NODES + 7) / 8, 256>>>(x, eps, i, use_gx);
        mlp_kernel<<<(N_NODES + BM - 1) / BM, 256>>>(
            x,
            W1 + (size_t)i * HID * HID, b1 + (size_t)i * HID,
            W2 + (size_t)i * HID * HID, b2 + (size_t)i * HID,
            (i > 0) ? 1 : 0, use_gx);
    }

    pool_kernel<<<(N_NODES + POOL_CHUNK - 1) / POOL_CHUNK, 128>>>(batch);
    cls1_kernel<<<NUM_GRAPHS, 128>>>(Wc1, bc1);
    cls2_kernel<<<1, 128>>>(Wc2, bc2, (float*)d_out);
}

// round 15
// speedup vs baseline: 1.7369x; 1.0018x over previous
#include <cuda_runtime.h>
#include <cstdint>

#define N_NODES 100000
#define N_EDGES 1600000
#define HID 128
#define NUM_LAYERS 10
#define NUM_GRAPHS 64
#define NUM_CLASSES 2

// ---------------- scratch (device globals; no runtime allocation) ----------------
__device__ __align__(16) float g_x[(size_t)N_NODES * HID];   // ping-pong buf A
__device__ __align__(16) float g_y[(size_t)N_NODES * HID];   // ping-pong buf B
__device__ int   g_deg[N_NODES];
__device__ int   g_rowptr[N_NODES + 1];
__device__ int   g_fill[N_NODES];
__device__ int   g_ssrc[N_EDGES];
__device__ int   g_bsums[256];
__device__ __align__(16) float g_pool[NUM_GRAPHS * HID];
__device__ float g_cnt[NUM_GRAPHS];
__device__ __align__(16) float g_cls[NUM_GRAPHS * HID];

// ---------------- CSR build ----------------
__global__ void zero_kernel() {
    int i = blockIdx.x * blockDim.x + threadIdx.x;
    if (i < N_NODES) g_deg[i] = 0;
    if (i < NUM_GRAPHS * HID) g_pool[i] = 0.f;
    if (i < NUM_GRAPHS) g_cnt[i] = 0.f;
}

__global__ void hist_kernel(const int* __restrict__ dst) {
    int e = blockIdx.x * blockDim.x + threadIdx.x;
    if (e < N_EDGES) atomicAdd(&g_deg[dst[e]], 1);
}

__global__ void scan1_kernel() {
    __shared__ int s[512];
    int tid = threadIdx.x;
    int i = blockIdx.x * 512 + tid;
    int v = (i < N_NODES) ? g_deg[i] : 0;
    s[tid] = v;
    __syncthreads();
    for (int off = 1; off < 512; off <<= 1) {
        int add = (tid >= off) ? s[tid - off] : 0;
        __syncthreads();
        s[tid] += add;
        __syncthreads();
    }
    if (i < N_NODES) g_rowptr[i] = s[tid] - v;
    if (tid == 511) g_bsums[blockIdx.x] = s[511];
}

__global__ void scan2_kernel(int nblk) {
    __shared__ int s[256];
    int tid = threadIdx.x;
    int v = (tid < nblk) ? g_bsums[tid] : 0;
    s[tid] = v;
    __syncthreads();
    for (int off = 1; off < 256; off <<= 1) {
        int add = (tid >= off) ? s[tid - off] : 0;
        __syncthreads();
        s[tid] += add;
        __syncthreads();
    }
    if (tid < nblk) g_bsums[tid] = s[tid] - v;
}

__global__ void scan3_kernel() {
    int i = blockIdx.x * blockDim.x + threadIdx.x;
    if (i < N_NODES) {
        int rp = g_rowptr[i] + g_bsums[i >> 9];
        g_rowptr[i] = rp;
        g_fill[i] = rp;
    }
    if (i == 0) g_rowptr[N_NODES] = N_EDGES;
}

__global__ void scatter_kernel(const int* __restrict__ src,
                               const int* __restrict__ dst) {
    int e = blockIdx.x * blockDim.x + threadIdx.x;
    if (e < N_EDGES) {
        int d = dst[e];
        int p = atomicAdd(&g_fill[d], 1);
        g_ssrc[p] = src[e];
    }
}

// ======== fused layer kernel: gather (CSR) + 2-GEMM MLP + residuals ==============
// Block owns 64 rows. Phase 1: 8 warps gather h = (1+eps)*x + sum_in x into smem.
// Phase 2: R6 FFMA GEMM core. Ping-pong x between g_x/g_y (no in-place race).
// Blocks in different phases overlap memory-bound gather with issue-bound GEMM.
#define BM 64
#define HSTR 132  // padded row stride in floats

__global__ void __launch_bounds__(256, 2)
layer_kernel(const float* __restrict__ xin_ext,
             const float* __restrict__ eps,
             const float* __restrict__ W1, const float* __restrict__ b1,
             const float* __restrict__ W2, const float* __restrict__ b2,
             int layer) {
    __shared__ float Bs[BM * HSTR];

    int t = threadIdx.x;
    int w = t >> 5, lane = t & 31;
    int row0 = blockIdx.x * BM;

    // ping-pong: layer 0 reads input, writes g_y; odd layers read g_y write g_x; ...
    const float* src = (layer == 0) ? xin_ext : ((layer & 1) ? g_y : g_x);
    float* dstbuf = (layer & 1) ? g_x : g_y;
    int add_h = (layer > 0) ? 1 : 0;

    float ep1 = 1.0f + eps[layer];
    const float4* xv = (const float4*)src;

    // ---- phase 1: gather 64 rows (warp per node, 8 rounds) ----
    for (int round = 0; round < 8; round++) {
        int lr = round * 8 + w;
        int node = row0 + lr;
        float4 a0 = make_float4(0.f, 0.f, 0.f, 0.f);
        if (node < N_NODES) {
            float4 b = __ldg(&xv[(size_t)node * 32 + lane]);
            a0 = make_float4(b.x * ep1, b.y * ep1, b.z * ep1, b.w * ep1);
            float4 a1 = make_float4(0.f, 0.f, 0.f, 0.f);
            float4 a2 = a1, a3 = a1;
            int s = g_rowptr[node], e = g_rowptr[node + 1];
            int i = s;
            for (; i + 4 <= e; i += 4) {
                int s0 = g_ssrc[i], s1 = g_ssrc[i + 1];
                int s2 = g_ssrc[i + 2], s3 = g_ssrc[i + 3];
                float4 v0 = __ldg(&xv[(size_t)s0 * 32 + lane]);
                float4 v1 = __ldg(&xv[(size_t)s1 * 32 + lane]);
                float4 v2 = __ldg(&xv[(size_t)s2 * 32 + lane]);
                float4 v3 = __ldg(&xv[(size_t)s3 * 32 + lane]);
                a0.x += v0.x; a0.y += v0.y; a0.z += v0.z; a0.w += v0.w;
                a1.x += v1.x; a1.y += v1.y; a1.z += v1.z; a1.w += v1.w;
                a2.x += v2.x; a2.y += v2.y; a2.z += v2.z; a2.w += v2.w;
                a3.x += v3.x; a3.y += v3.y; a3.z += v3.z; a3.w += v3.w;
            }
            for (; i < e; i++) {
                int s0 = g_ssrc[i];
                float4 v0 = __ldg(&xv[(size_t)s0 * 32 + lane]);
                a1.x += v0.x; a1.y += v0.y; a1.z += v0.z; a1.w += v0.w;
            }
            a0.x += a1.x + a2.x + a3.x;
            a0.y += a1.y + a2.y + a3.y;
            a0.z += a1.z + a2.z + a3.z;
            a0.w += a1.w + a2.w + a3.w;
        }
        *((float4*)&Bs[lr * HSTR + lane * 4]) = a0;
    }
    __syncthreads();

    // ---- phase 2: MLP (R6 FFMA core) ----
    int tx = t & 15, ty = t >> 4;   // 16 x 16 thread grid
    int cb = tx * 8;                // 8 cols per thread
    int rb = ty * 4;                // 4 rows per thread
    int nrows = N_NODES - row0; if (nrows > BM) nrows = BM;

    float acc[4][8];
#pragma unroll
    for (int r = 0; r < 4; r++)
#pragma unroll
        for (int c = 0; c < 8; c++) acc[r][c] = 0.f;

#pragma unroll 4
    for (int k = 0; k < 128; k++) {
        float a[4];
#pragma unroll
        for (int r = 0; r < 4; r++) a[r] = Bs[(rb + r) * HSTR + k];
        float4 w0 = __ldg((const float4*)&W1[k * 128 + cb]);
        float4 w1 = __ldg((const float4*)&W1[k * 128 + cb + 4]);
        float bv[8] = {w0.x, w0.y, w0.z, w0.w, w1.x, w1.y, w1.z, w1.w};
#pragma unroll
        for (int r = 0; r < 4; r++)
#pragma unroll
            for (int c = 0; c < 8; c++) acc[r][c] += a[r] * bv[c];
    }

    // save this thread's h values for the MLP residual before Bs is overwritten
    float4 hreg[4][2];
#pragma unroll
    for (int r = 0; r < 4; r++) {
        hreg[r][0] = *((float4*)&Bs[(rb + r) * HSTR + cb]);
        hreg[r][1] = *((float4*)&Bs[(rb + r) * HSTR + cb + 4]);
    }
    __syncthreads();  // all GEMM1 + h-copy reads of Bs done

    // write T = relu(acc + b1) into the SAME buffer
#pragma unroll
    for (int r = 0; r < 4; r++)
#pragma unroll
        for (int c = 0; c < 8; c++) {
            float v = acc[r][c] + __ldg(&b1[cb + c]);
            Bs[(rb + r) * HSTR + cb + c] = fmaxf(v, 0.f);
        }
    __syncthreads();

#pragma unroll
    for (int r = 0; r < 4; r++)
#pragma unroll
        for (int c = 0; c < 8; c++) acc[r][c] = 0.f;

#pragma unroll 4
    for (int k = 0; k < 128; k++) {
        float a[4];
#pragma unroll
        for (int r = 0; r < 4; r++) a[r] = Bs[(rb + r) * HSTR + k];
        float4 w0 = __ldg((const float4*)&W2[k * 128 + cb]);
        float4 w1 = __ldg((const float4*)&W2[k * 128 + cb + 4]);
        float bv[8] = {w0.x, w0.y, w0.z, w0.w, w1.x, w1.y, w1.z, w1.w};
#pragma unroll
        for (int r = 0; r < 4; r++)
#pragma unroll
            for (int c = 0; c < 8; c++) acc[r][c] += a[r] * bv[c];
    }

    // epilogue: out = relu(acc + b2 [+ h]) + xin  -> dstbuf
#pragma unroll
    for (int r = 0; r < 4; r++) {
        int row = rb + r;
        if (row < nrows) {
            size_t base = (size_t)(row0 + row) * HID + cb;
            float hv[8] = {hreg[r][0].x, hreg[r][0].y, hreg[r][0].z, hreg[r][0].w,
                           hreg[r][1].x, hreg[r][1].y, hreg[r][1].z, hreg[r][1].w};
            float4 xi0 = __ldg((const float4*)(src + base));
            float4 xi1 = __ldg((const float4*)(src + base + 4));
            float xvv[8] = {xi0.x, xi0.y, xi0.z, xi0.w, xi1.x, xi1.y, xi1.z, xi1.w};
            float o[8];
#pragma unroll
            for (int c = 0; c < 8; c++) {
                float v = acc[r][c] + __ldg(&b2[cb + c]);
                if (add_h) v += hv[c];
                o[c] = fmaxf(v, 0.f) + xvv[c];
            }
            *((float4*)(dstbuf + base))     = make_float4(o[0], o[1], o[2], o[3]);
            *((float4*)(dstbuf + base + 4)) = make_float4(o[4], o[5], o[6], o[7]);
        }
    }
}

// ---------------- mean pool over sorted batch (reads g_x — final buffer) ----------
#define POOL_CHUNK 256
__global__ void pool_kernel(const int* __restrict__ batch) {
    int d = threadIdx.x;  // 128
    int n0 = blockIdx.x * POOL_CHUNK;
    int n1 = n0 + POOL_CHUNK; if (n1 > N_NODES) n1 = N_NODES;
    int cur = batch[n0];
    float local = 0.f;
    for (int n = n0; n < n1; n++) {
        int b = batch[n];
        if (b != cur) {
            atomicAdd(&g_pool[cur * HID + d], local);
            local = 0.f; cur = b;
        }
        local += g_x[(size_t)n * HID + d];
    }
    atomicAdd(&g_pool[cur * HID + d], local);
    if (d == 0) {
        int c2 = batch[n0];
        float cl = 0.f;
        for (int n = n0; n < n1; n++) {
            int b = batch[n];
            if (b != c2) { atomicAdd(&g_cnt[c2], cl); cl = 0.f; c2 = b; }
            cl += 1.f;
        }
        atomicAdd(&g_cnt[c2], cl);
    }
}

// ---------------- classifier ----------------
__global__ void cls1_kernel(const float* __restrict__ Wc1,
                            const float* __restrict__ bc1) {
    __shared__ float Ps[128];
    int g = blockIdx.x;
    int t = threadIdx.x;
    float inv = 1.f / fmaxf(g_cnt[g], 1.f);
    Ps[t] = g_pool[g * HID + t] * inv;
    __syncthreads();
    float s = bc1[t];
#pragma unroll 4
    for (int k = 0; k < 128; k++) s += Ps[k] * __ldg(&Wc1[k * 128 + t]);
    g_cls[g * HID + t] = fmaxf(s, 0.f);
}

__global__ void cls2_kernel(const float* __restrict__ Wc2,
                            const float* __restrict__ bc2,
                            float* __restrict__ out) {
    int t = threadIdx.x;
    int g = t >> 1, c = t & 1;
    float s = bc2[c];
#pragma unroll 4
    for (int k = 0; k < 128; k++) s += g_cls[g * HID + k] * __ldg(&Wc2[k * 2 + c]);
    out[t] = s;
}

// ---------------- launch (pure kernel launches — graph-capture safe) -------------
// NOTE: never do pointer arithmetic on __device__ symbols here (host shadow trap).
extern "C" void kernel_launch(void* const* d_in, const int* in_sizes, int n_in,
                              void* d_out, int out_size) {
    const float* x     = (const float*)d_in[0];
    const int*   ei    = (const int*)d_in[1];     // int32 (JAX x64 disabled)
    const int*   batch = (const int*)d_in[2];     // int32
    const float* eps   = (const float*)d_in[3];
    const float* W1    = (const float*)d_in[4];
    const float* b1    = (const float*)d_in[5];
    const float* W2    = (const float*)d_in[6];
    const float* b2    = (const float*)d_in[7];
    const float* Wc1   = (const float*)d_in[8];
    const float* bc1   = (const float*)d_in[9];
    const float* Wc2   = (const float*)d_in[10];
    const float* bc2   = (const float*)d_in[11];
    const int* src = ei;
    const int* dst = ei + N_EDGES;

    const int nblk_scan = (N_NODES + 511) / 512;  // 196
    const int nblk_mlp  = (N_NODES + BM - 1) / BM;  // 1563

    zero_kernel<<<(N_NODES + 255) / 256, 256>>>();
    hist_kernel<<<(N_EDGES + 255) / 256, 256>>>(dst);
    scan1_kernel<<<nblk_scan, 512>>>();
    scan2_kernel<<<1, 256>>>(nblk_scan);
    scan3_kernel<<<(N_NODES + 255) / 256, 256>>>();
    scatter_kernel<<<(N_EDGES + 255) / 256, 256>>>(src, dst);

    for (int i = 0; i < NUM_LAYERS; i++) {
        layer_kernel<<<nblk_mlp, 256>>>(
            x, eps,
            W1 + (size_t)i * HID * HID, b1 + (size_t)i * HID,
            W2 + (size_t)i * HID * HID, b2 + (size_t)i * HID,
            i);
    }

    pool_kernel<<<(N_NODES + POOL_CHUNK - 1) / POOL_CHUNK, 128>>>(batch);
    cls1_kernel<<<NUM_GRAPHS, 128>>>(Wc1, bc1);
    cls2_kernel<<<1, 128>>>(Wc2, bc2, (float*)d_out);
}